// round 7
// baseline (speedup 1.0000x reference)
#include <cuda_runtime.h>
#include <cstdint>
#include <cstddef>

// DPLoss: mean over B rows of [ sum_{j<len[i]} (pred[i,j]-log(align[i,j]))^2 / len[i] ]
// B=4096, T=2048, fp32.
//
// R7: TMA (cp.async.bulk 1D) + mbarrier smem pipeline. Memory pipeline lives
// in the TMA engine + smem ring (5 stages x 4KB/CTA, 160KB in flight per SM),
// not in the register file -- which capped every LDG variant at ~60% DRAM.
// Single-wave grid (1184 = 148x8), quarter-row units (16384), <=2% tail.

#define B_ROWS   4096
#define T_COLS   2048
#define UNIT_F   512                     // floats per unit (quarter row)
#define UNIT_B   2048                    // bytes per stream per unit
#define UNITS    (B_ROWS * 4)            // 16384
#define NTHREADS 256
#define NCTAS    1184                    // 148 SMs * 8 CTA/SM, single wave
#define STAGES   5

__device__ float    g_acc = 0.0f;
__device__ unsigned g_count = 0;

__device__ __forceinline__ uint32_t smem_u32(const void* p) {
    uint32_t a;
    asm("{ .reg .u64 t; cvta.to.shared.u64 t, %1; cvt.u32.u64 %0, t; }"
        : "=r"(a) : "l"(p));
    return a;
}
__device__ __forceinline__ void mbar_init(uint32_t bar, uint32_t cnt) {
    asm volatile("mbarrier.init.shared.b64 [%0], %1;" :: "r"(bar), "r"(cnt) : "memory");
}
__device__ __forceinline__ void mbar_expect_tx(uint32_t bar, uint32_t bytes) {
    asm volatile("mbarrier.arrive.expect_tx.shared.b64 _, [%0], %1;"
                 :: "r"(bar), "r"(bytes) : "memory");
}
__device__ __forceinline__ void bulk_g2s(uint32_t dst, const void* src,
                                         uint32_t bytes, uint32_t bar) {
    asm volatile(
        "cp.async.bulk.shared::cluster.global.mbarrier::complete_tx::bytes "
        "[%0], [%1], %2, [%3];"
        :: "r"(dst), "l"(src), "r"(bytes), "r"(bar) : "memory");
}
__device__ __forceinline__ void mbar_wait(uint32_t bar, uint32_t parity) {
    asm volatile(
        "{\n\t"
        ".reg .pred P;\n\t"
        "WL_%=:\n\t"
        "mbarrier.try_wait.parity.acquire.cta.shared::cta.b64 P, [%0], %1;\n\t"
        "@!P bra WL_%=;\n\t"
        "}"
        :: "r"(bar), "r"(parity) : "memory");
}

__global__ __launch_bounds__(NTHREADS, 8) void dploss_kernel(
    const float* __restrict__ pred,
    const float* __restrict__ align,
    const int* __restrict__ lens,
    float* __restrict__ out)
{
    __shared__ __align__(16) float sp[STAGES][UNIT_F];   // pred stages
    __shared__ __align__(16) float sa[STAGES][UNIT_F];   // align stages
    __shared__ __align__(8)  unsigned long long bars[STAGES];
    __shared__ float warp_sums[NTHREADS / 32];

    const int tid = threadIdx.x;
    const int bid = blockIdx.x;
    // units per CTA: bid + k*NCTAS < UNITS
    const int nk = (bid < (UNITS - 13 * NCTAS)) ? 14 : 13;   // 16384-15392=992

    if (tid == 0) {
        #pragma unroll
        for (int s = 0; s < STAGES; ++s)
            mbar_init(smem_u32(&bars[s]), 1);
    }
    __syncthreads();

    // prologue: fill the pipeline
    if (tid == 0) {
        #pragma unroll
        for (int n = 0; n < STAGES; ++n) {      // nk >= 13 > STAGES always
            const int u = bid + n * NCTAS;
            const uint32_t bar = smem_u32(&bars[n]);
            mbar_expect_tx(bar, 2 * UNIT_B);
            bulk_g2s(smem_u32(&sp[n][0]), pred  + (size_t)u * UNIT_F, UNIT_B, bar);
            bulk_g2s(smem_u32(&sa[n][0]), align + (size_t)u * UNIT_F, UNIT_B, bar);
        }
    }

    float acc = 0.0f;

    for (int n = 0; n < nk; ++n) {
        const int s = n % STAGES;
        const int u = bid + n * NCTAS;
        const uint32_t bar = smem_u32(&bars[s]);
        const uint32_t parity = (n >= STAGES) ? ((n / STAGES) & 1u) : 0u;
        mbar_wait(bar, parity);

        const int row = u >> 2;                         // 4 units per row
        const int len = __ldg(lens + row);
        const int j   = ((u & 3) << 9) + (tid << 1);    // element index in row

        const float2 pv = *(const float2*)&sp[s][tid << 1];
        const float2 av = *(const float2*)&sa[s][tid << 1];

        float d0 = pv.x - __logf(av.x);
        float d1 = pv.y - __logf(av.y);
        float rs = 0.0f;
        if (j + 0 < len) rs += d0 * d0;
        if (j + 1 < len) rs += d1 * d1;
        acc += rs * __fdividef(1.0f, (float)len);

        __syncthreads();   // all threads done reading stage s

        if (tid == 0 && n + STAGES < nk) {
            const int u2 = bid + (n + STAGES) * NCTAS;
            mbar_expect_tx(bar, 2 * UNIT_B);
            bulk_g2s(smem_u32(&sp[s][0]), pred  + (size_t)u2 * UNIT_F, UNIT_B, bar);
            bulk_g2s(smem_u32(&sa[s][0]), align + (size_t)u2 * UNIT_F, UNIT_B, bar);
        }
    }

    // warp reduction
    #pragma unroll
    for (int off = 16; off > 0; off >>= 1)
        acc += __shfl_down_sync(0xFFFFFFFFu, acc, off);

    const int wid = tid >> 5;
    const int lid = tid & 31;
    if (lid == 0) warp_sums[wid] = acc;
    __syncthreads();

    if (wid == 0) {
        float v = (lid < NTHREADS / 32) ? warp_sums[lid] : 0.0f;
        #pragma unroll
        for (int off = 4; off > 0; off >>= 1)
            v += __shfl_down_sync(0xFFFFFFFFu, v, off);

        if (lid == 0) {
            atomicAdd(&g_acc, v);
            __threadfence();
            unsigned prev = atomicInc(&g_count, NCTAS - 1);
            if (prev == NCTAS - 1) {
                float total = atomicExch(&g_acc, 0.0f);   // read + reset for replay
                *out = total * (1.0f / (float)B_ROWS);
            }
        }
    }
}

extern "C" void kernel_launch(void* const* d_in, const int* in_sizes, int n_in,
                              void* d_out, int out_size)
{
    const float* pred  = (const float*)d_in[0];
    const float* align = (const float*)d_in[1];
    const int*   lens  = (const int*)d_in[2];
    float* out = (float*)d_out;

    dploss_kernel<<<NCTAS, NTHREADS>>>(pred, align, lens, out);
}

// round 8
// speedup vs baseline: 1.6290x; 1.6290x over previous
#include <cuda_runtime.h>
#include <cstddef>

// DPLoss: mean over B rows of [ sum_{j<len[i]} (pred[i,j]-log(align[i,j]))^2 / len[i] ]
// B=4096, T=2048, fp32, len ~ U[1,2048].
//
// R8 key insight: positions j >= len[i] contribute ZERO, and E[len] ~ T/2,
// so loading only each row's prefix halves the HBM traffic (67MB -> ~34MB).
// Variable per-row work is balanced with a dynamic ticket counter; the next
// ticket + its len are prefetched into double-buffered smem by thread 0 so
// the atomic's latency overlaps current-row processing. One barrier per row.
// Ticket/accumulator self-reset via last-CTA-out (CUDA-graph replay safe).

#define B_ROWS   4096
#define T_VEC4   512                  // float4 per full row
#define NTHREADS 256
#define NCTAS    1184                 // 148 SMs * 8 CTA/SM, single wave

__device__ float    g_acc    = 0.0f;
__device__ unsigned g_count  = 0;
__device__ unsigned g_ticket = 0;

__global__ __launch_bounds__(NTHREADS) void dploss_kernel(
    const float4* __restrict__ pred,
    const float4* __restrict__ align,
    const int* __restrict__ lens,
    float* __restrict__ out)
{
    __shared__ int   s_row[2];
    __shared__ int   s_len[2];
    __shared__ float warp_sums[NTHREADS / 32];

    const int tid = threadIdx.x;

    // initial ticket
    if (tid == 0) {
        unsigned t = atomicAdd(&g_ticket, 1u);
        int r = (t < B_ROWS) ? (int)t : -1;
        s_row[0] = r;
        s_len[0] = (r >= 0) ? __ldg(lens + r) : 0;
    }
    __syncthreads();

    float acc = 0.0f;
    int buf = 0;

    while (true) {
        const int row = s_row[buf];
        if (row < 0) break;
        const int len = s_len[buf];

        // prefetch next work item; latency hides under this row's processing
        if (tid == 0) {
            unsigned t = atomicAdd(&g_ticket, 1u);
            int r = (t < B_ROWS) ? (int)t : -1;
            s_row[buf ^ 1] = r;
            s_len[buf ^ 1] = (r >= 0) ? __ldg(lens + r) : 0;
        }

        const int nvec = (len + 3) >> 2;           // float4s actually needed
        const float4* __restrict__ p = pred  + (size_t)row * T_VEC4;
        const float4* __restrict__ a = align + (size_t)row * T_VEC4;
        const float inv_len = __fdividef(1.0f, (float)len);

        float rs = 0.0f;

        if (tid < nvec) {                          // chunk 0: elems [0,1024)
            float4 pv = p[tid];
            float4 av = a[tid];
            const int j = tid << 2;                // j < len guaranteed
            float d0 = pv.x - __logf(av.x);
            float d1 = pv.y - __logf(av.y);
            float d2 = pv.z - __logf(av.z);
            float d3 = pv.w - __logf(av.w);
            rs += d0 * d0;
            if (j + 1 < len) rs += d1 * d1;
            if (j + 2 < len) rs += d2 * d2;
            if (j + 3 < len) rs += d3 * d3;
        }
        const int i2 = tid + NTHREADS;
        if (i2 < nvec) {                           // chunk 1: elems [1024,2048)
            float4 pv = p[i2];
            float4 av = a[i2];
            const int j = i2 << 2;                 // j < len guaranteed
            float d0 = pv.x - __logf(av.x);
            float d1 = pv.y - __logf(av.y);
            float d2 = pv.z - __logf(av.z);
            float d3 = pv.w - __logf(av.w);
            rs += d0 * d0;
            if (j + 1 < len) rs += d1 * d1;
            if (j + 2 < len) rs += d2 * d2;
            if (j + 3 < len) rs += d3 * d3;
        }

        acc += rs * inv_len;

        buf ^= 1;
        __syncthreads();    // publish prefetched ticket, recycle smem slot
    }

    // warp reduction
    #pragma unroll
    for (int off = 16; off > 0; off >>= 1)
        acc += __shfl_down_sync(0xFFFFFFFFu, acc, off);

    const int wid = tid >> 5;
    const int lid = tid & 31;
    if (lid == 0) warp_sums[wid] = acc;
    __syncthreads();

    if (wid == 0) {
        float v = (lid < NTHREADS / 32) ? warp_sums[lid] : 0.0f;
        #pragma unroll
        for (int off = 4; off > 0; off >>= 1)
            v += __shfl_down_sync(0xFFFFFFFFu, v, off);

        if (lid == 0) {
            atomicAdd(&g_acc, v);
            __threadfence();
            unsigned prev = atomicInc(&g_count, NCTAS - 1);
            if (prev == NCTAS - 1) {
                // all CTAs done: every ticket grab precedes its CTA's arrive
                float total = atomicExch(&g_acc, 0.0f);   // read + reset
                g_ticket = 0;                             // reset for replay
                *out = total * (1.0f / (float)B_ROWS);
            }
        }
    }
}

extern "C" void kernel_launch(void* const* d_in, const int* in_sizes, int n_in,
                              void* d_out, int out_size)
{
    const float4* pred  = (const float4*)d_in[0];
    const float4* align = (const float4*)d_in[1];
    const int*    lens  = (const int*)d_in[2];
    float* out = (float*)d_out;

    dploss_kernel<<<NCTAS, NTHREADS>>>(pred, align, lens, out);
}